// round 6
// baseline (speedup 1.0000x reference)
#include <cuda_runtime.h>
#include <cstdint>

#define BSZ 32
#define SEQ_LEN 4096
#define EMBED_DIM 1024
#define PAD_IDX 1
#define SEP_ID 4

#define ROWS_PER_BLK 4
#define F4_PER_ROW (EMBED_DIM / 4)       // 256
#define NPOS_BLOCKS BSZ                  // 32 positions blocks
#define NGATHER_BLOCKS ((BSZ * SEQ_LEN) / ROWS_PER_BLK)  // 32768
#define TOK_PER_THREAD (SEQ_LEN / 256)   // 16

// Scratch (allocation-free rule: device globals).
__device__ int g_pos[BSZ * SEQ_LEN];
__device__ int g_flag[BSZ];   // zeroed by memsetAsync each call; 1 = row ready

// ---------------------------------------------------------------------------
// Fused kernel.
//   blocks [0, 32):        positions — per-row scan, 256 thr x 16 tokens,
//                          then release g_flag[row].
//   blocks [32, 32+32768): gather — thread 0 polls one flag (nanosleep
//                          backoff), acquire fence, then MLP=4 copy with
//                          evict-first stores.
// ---------------------------------------------------------------------------
__global__ __launch_bounds__(256, 8)
void fused_kernel(const int* __restrict__ tok32,
                  const float4* __restrict__ w,
                  float4* __restrict__ out) {
    const int bid = blockIdx.x;
    const int t   = threadIdx.x;

    if (bid < NPOS_BLOCKS) {
        // ================= positions role =================
        const int row  = bid;
        const int lane = t & 31;
        const int warp = t >> 5;

        __shared__ int s_fp[8];
        __shared__ int s_ls[8];
        __shared__ int s_is64;

        // dtype probe: int64 tokens have zero high words for values < 2^31
        if (t == 0) {
            int odd_nonzero = 0;
            #pragma unroll
            for (int k = 1; k < 64; k += 2) odd_nonzero |= tok32[k];
            s_is64 = (odd_nonzero == 0) ? 1 : 0;
        }
        __syncthreads();
        const int is64 = s_is64;

        // load my 16 contiguous tokens
        const int base = t * TOK_PER_THREAD;
        int tk[TOK_PER_THREAD];
        if (is64) {
            const longlong2* p = (const longlong2*)
                ((const long long*)tok32 + (size_t)row * SEQ_LEN + base);
            #pragma unroll
            for (int q = 0; q < TOK_PER_THREAD / 2; q++) {
                longlong2 a = p[q];
                tk[2 * q]     = (int)a.x;
                tk[2 * q + 1] = (int)a.y;
            }
        } else {
            const int4* p = (const int4*)(tok32 + (size_t)row * SEQ_LEN + base);
            #pragma unroll
            for (int q = 0; q < TOK_PER_THREAD / 4; q++) {
                int4 a = p[q];
                tk[4 * q] = a.x; tk[4 * q + 1] = a.y;
                tk[4 * q + 2] = a.z; tk[4 * q + 3] = a.w;
            }
        }

        // local aggregate: fp = min PAD idx, ls = max SEP idx
        int fp = 0x7fffffff, ls = 0;
        #pragma unroll
        for (int e = 0; e < TOK_PER_THREAD; e++) {
            int j = base + e;
            if (tk[e] == PAD_IDX) fp = min(fp, j);
            if (tk[e] == SEP_ID)  ls = max(ls, j);
        }

        // inclusive warp scan
        int ifp = fp, ils = ls;
        #pragma unroll
        for (int d = 1; d < 32; d <<= 1) {
            int ofp = __shfl_up_sync(0xffffffffu, ifp, d);
            int ols = __shfl_up_sync(0xffffffffu, ils, d);
            if (lane >= d) { ifp = min(ifp, ofp); ils = max(ils, ols); }
        }
        if (lane == 31) { s_fp[warp] = ifp; s_ls[warp] = ils; }
        __syncthreads();

        // exclusive prefix across the 8 warps
        int exfp = 0x7fffffff, exls = 0;
        #pragma unroll
        for (int wsel = 0; wsel < 7; wsel++) {
            if (warp > wsel) { exfp = min(exfp, s_fp[wsel]); exls = max(exls, s_ls[wsel]); }
        }
        // lane-exclusive within warp
        int lfp = __shfl_up_sync(0xffffffffu, ifp, 1);
        int lls = __shfl_up_sync(0xffffffffu, ils, 1);
        if (lane > 0) { exfp = min(exfp, lfp); exls = max(exls, lls); }

        // finalize my 16 elements
        int* po = g_pos + (size_t)row * SEQ_LEN;
        int fpx = exfp, lsx = exls;
        #pragma unroll
        for (int e = 0; e < TOK_PER_THREAD; e++) {
            int j = base + e;
            if (tk[e] == PAD_IDX) fpx = min(fpx, j);
            if (tk[e] == SEP_ID)  lsx = max(lsx, j);
            po[j] = (j < fpx) ? (j - lsx + 2) : 1;
        }

        // release: all block writes done -> visible -> flag
        __syncthreads();
        if (t == 0) {
            __threadfence();                       // cumulative release (gpu scope)
            *((volatile int*)&g_flag[row]) = 1;
        }
    } else {
        // ================= gather role =================
        const int row0 = (bid - NPOS_BLOCKS) * ROWS_PER_BLK;
        const int b    = row0 >> 12;               // batch row (4096 j's per b)

        // single-thread poll with backoff; acquire fence; broadcast via bar
        if (t == 0) {
            const volatile int* vf = &g_flag[b];
            while (*vf == 0) __nanosleep(64);
            __threadfence();                       // acquire side
        }
        __syncthreads();

        // L2 loads for pos (L1 on this SM may hold a stale pre-release line)
        const int* pp = g_pos + row0;
        int p0 = __ldcg(pp + 0);
        int p1 = __ldcg(pp + 1);
        int p2 = __ldcg(pp + 2);
        int p3 = __ldcg(pp + 3);

        // 4 independent loads in flight (L2 hits after first touch)
        float4 v0 = __ldg(w + (size_t)p0 * F4_PER_ROW + t);
        float4 v1 = __ldg(w + (size_t)p1 * F4_PER_ROW + t);
        float4 v2 = __ldg(w + (size_t)p2 * F4_PER_ROW + t);
        float4 v3 = __ldg(w + (size_t)p3 * F4_PER_ROW + t);

        // evict-first stores: keep the 16.8MB weights table L2-resident
        float4* dst = out + (size_t)row0 * F4_PER_ROW + t;
        __stcs(dst + 0 * F4_PER_ROW, v0);
        __stcs(dst + 1 * F4_PER_ROW, v1);
        __stcs(dst + 2 * F4_PER_ROW, v2);
        __stcs(dst + 3 * F4_PER_ROW, v3);
    }
}

extern "C" void kernel_launch(void* const* d_in, const int* in_sizes, int n_in,
                              void* d_out, int out_size) {
    const int*   tokens  = (const int*)d_in[0];     // int32 or int64 (probed)
    const float* weights = (const float*)d_in[1];   // [4098, 1024] f32
    float* out = (float*)d_out;                     // [32, 4096, 1024] f32

    // Reset only the 32 ready-flags (128 bytes).
    void* flag_addr = nullptr;
    cudaGetSymbolAddress(&flag_addr, g_flag);
    cudaMemsetAsync(flag_addr, 0, sizeof(int) * BSZ);

    fused_kernel<<<NPOS_BLOCKS + NGATHER_BLOCKS, 256>>>(
        tokens, (const float4*)weights, (float4*)out);
}

// round 7
// speedup vs baseline: 1.3387x; 1.3387x over previous
#include <cuda_runtime.h>
#include <cstdint>

#define BSZ 32
#define SEQ_LEN 4096
#define EMBED_DIM 1024
#define PAD_IDX 1
#define SEP_ID 4

// Scratch for computed positions (allocation-free rule: device global).
__device__ int g_pos[BSZ * SEQ_LEN];

// ---------------------------------------------------------------------------
// Kernel 1: positions. One block per batch row, 1024 threads, 4 tokens/thread.
// pos[j] = (no PAD in [0..j]) ? (j - lastSepIdx<=j + 2) : 1
// Triggers the dependent gather launch as soon as its stores are issued.
// ---------------------------------------------------------------------------
__global__ __launch_bounds__(1024, 1)
void positions_kernel(const int* __restrict__ tok32) {
    const int row  = blockIdx.x;
    const int t    = threadIdx.x;            // 0..1023
    const int lane = t & 31;
    const int warp = t >> 5;

    __shared__ int s_fp[32];
    __shared__ int s_ls[32];
    __shared__ int s_is64;

    // ---- dtype probe: int64 tokens have zero high words for values <2^31 ----
    if (t == 0) {
        int odd_nonzero = 0;
        #pragma unroll
        for (int k = 1; k < 64; k += 2) odd_nonzero |= tok32[k];
        s_is64 = (odd_nonzero == 0) ? 1 : 0;
    }
    __syncthreads();
    const int is64 = s_is64;

    // ---- load my 4 contiguous tokens ----
    const int base = t * 4;                  // local j within the row
    int tk[4];
    if (is64) {
        const longlong2* p =
            (const longlong2*)((const long long*)tok32 + (size_t)row * SEQ_LEN + base);
        longlong2 a = p[0];
        longlong2 b = p[1];
        tk[0] = (int)a.x; tk[1] = (int)a.y; tk[2] = (int)b.x; tk[3] = (int)b.y;
    } else {
        const int4* p = (const int4*)(tok32 + (size_t)row * SEQ_LEN + base);
        int4 a = p[0];
        tk[0] = a.x; tk[1] = a.y; tk[2] = a.z; tk[3] = a.w;
    }

    // ---- local aggregate: fp = min PAD idx, ls = max SEP idx ----
    int fp = 0x7fffffff;
    int ls = 0;
    #pragma unroll
    for (int e = 0; e < 4; e++) {
        int j = base + e;
        if (tk[e] == PAD_IDX) fp = min(fp, j);
        if (tk[e] == SEP_ID)  ls = max(ls, j);
    }

    // ---- inclusive warp scan (min/max) ----
    int ifp = fp, ils = ls;
    #pragma unroll
    for (int d = 1; d < 32; d <<= 1) {
        int ofp = __shfl_up_sync(0xffffffffu, ifp, d);
        int ols = __shfl_up_sync(0xffffffffu, ils, d);
        if (lane >= d) { ifp = min(ifp, ofp); ils = max(ils, ols); }
    }
    if (lane == 31) { s_fp[warp] = ifp; s_ls[warp] = ils; }
    __syncthreads();

    // ---- scan warp aggregates (warp 0) ----
    if (warp == 0) {
        int wfp = s_fp[lane], wls = s_ls[lane];
        #pragma unroll
        for (int d = 1; d < 32; d <<= 1) {
            int ofp = __shfl_up_sync(0xffffffffu, wfp, d);
            int ols = __shfl_up_sync(0xffffffffu, wls, d);
            if (lane >= d) { wfp = min(wfp, ofp); wls = max(wls, ols); }
        }
        s_fp[lane] = wfp; s_ls[lane] = wls;
    }
    __syncthreads();

    // ---- exclusive prefix for this thread ----
    int exfp = 0x7fffffff, exls = 0;
    if (warp > 0) { exfp = s_fp[warp - 1]; exls = s_ls[warp - 1]; }
    int lfp = __shfl_up_sync(0xffffffffu, ifp, 1);
    int lls = __shfl_up_sync(0xffffffffu, ils, 1);
    if (lane > 0) { exfp = min(exfp, lfp); exls = max(exls, lls); }

    // ---- finalize my 4 elements ----
    int* out = g_pos + (size_t)row * SEQ_LEN;
    int fpx = exfp, lsx = exls;
    #pragma unroll
    for (int e = 0; e < 4; e++) {
        int j = base + e;
        if (tk[e] == PAD_IDX) fpx = min(fpx, j);
        if (tk[e] == SEP_ID)  lsx = max(lsx, j);
        out[j] = (j < fpx) ? (j - lsx + 2) : 1;
    }

    // PDL: allow the dependent gather grid to start launching now.
    cudaTriggerProgrammaticLaunchCompletion();
}

// ---------------------------------------------------------------------------
// Kernel 2: gather. 4 rows per block of 256 threads; thread t copies float4
// column t of each row. 4 independent LDG.128 (MLP=4) then 4 STG.128 with
// evict-first (__stcs) so the 512MB output stream doesn't evict the 16.8MB
// weights table from L2. Opens with the PDL grid-dependency wait.
// ---------------------------------------------------------------------------
#define ROWS_PER_BLK 4
#define F4_PER_ROW (EMBED_DIM / 4)   // 256

__global__ __launch_bounds__(256, 8)
void gather_kernel(const float4* __restrict__ w, float4* __restrict__ out) {
    // Hardware-backed wait for the positions grid (writes then visible).
    cudaGridDependencySynchronize();

    const int row0 = blockIdx.x * ROWS_PER_BLK;
    const int t    = threadIdx.x;

    const int p0 = g_pos[row0 + 0];
    const int p1 = g_pos[row0 + 1];
    const int p2 = g_pos[row0 + 2];
    const int p3 = g_pos[row0 + 3];

    float4 v0 = __ldg(w + (size_t)p0 * F4_PER_ROW + t);
    float4 v1 = __ldg(w + (size_t)p1 * F4_PER_ROW + t);
    float4 v2 = __ldg(w + (size_t)p2 * F4_PER_ROW + t);
    float4 v3 = __ldg(w + (size_t)p3 * F4_PER_ROW + t);

    float4* dst = out + (size_t)row0 * F4_PER_ROW + t;
    __stcs(dst + 0 * F4_PER_ROW, v0);
    __stcs(dst + 1 * F4_PER_ROW, v1);
    __stcs(dst + 2 * F4_PER_ROW, v2);
    __stcs(dst + 3 * F4_PER_ROW, v3);
}

extern "C" void kernel_launch(void* const* d_in, const int* in_sizes, int n_in,
                              void* d_out, int out_size) {
    const int*   tokens  = (const int*)d_in[0];     // int32 or int64 (probed)
    const float* weights = (const float*)d_in[1];   // [4098, 1024] f32
    float* out = (float*)d_out;                     // [32, 4096, 1024] f32

    positions_kernel<<<BSZ, 1024>>>(tokens);

    // Gather launched with programmatic stream serialization (PDL): its blocks
    // may begin launching once positions_kernel triggers completion.
    cudaLaunchConfig_t cfg = {};
    cfg.gridDim  = dim3((BSZ * SEQ_LEN) / ROWS_PER_BLK, 1, 1);
    cfg.blockDim = dim3(256, 1, 1);
    cfg.dynamicSmemBytes = 0;
    cfg.stream = 0;

    cudaLaunchAttribute attrs[1];
    attrs[0].id = cudaLaunchAttributeProgrammaticStreamSerialization;
    attrs[0].val.programmaticStreamSerializationAllowed = 1;
    cfg.attrs = attrs;
    cfg.numAttrs = 1;

    cudaLaunchKernelEx(&cfg, gather_kernel,
                       (const float4*)weights, (float4*)out);
}